// round 7
// baseline (speedup 1.0000x reference)
#include <cuda_runtime.h>
#include <cstdint>

typedef unsigned long long u64;

// ---------------- f32x2 packed helpers (sm_103a) ----------------
__device__ __forceinline__ u64 pack2(float x, float y) {
    u64 r; asm("mov.b64 %0, {%1,%2};" : "=l"(r) : "f"(x), "f"(y)); return r;
}
__device__ __forceinline__ void unpack2(u64 v, float& x, float& y) {
    asm("mov.b64 {%0,%1}, %2;" : "=f"(x), "=f"(y) : "l"(v));
}
__device__ __forceinline__ u64 fma2(u64 a, u64 b, u64 c) {
    u64 d; asm("fma.rn.f32x2 %0,%1,%2,%3;" : "=l"(d) : "l"(a), "l"(b), "l"(c)); return d;
}
__device__ __forceinline__ u64 mul2(u64 a, u64 b) {
    u64 d; asm("mul.rn.f32x2 %0,%1,%2;" : "=l"(d) : "l"(a), "l"(b)); return d;
}
__device__ __forceinline__ u64 add2(u64 a, u64 b) {
    u64 d; asm("add.rn.f32x2 %0,%1,%2;" : "=l"(d) : "l"(a), "l"(b)); return d;
}

// Problem constants (B=4, C=64, H=W=256, K=7)
#define HH 256
#define WW 256
#define CC 64
#define PAD 3
#define TILE_W 32
#define TILE_H 16
#define HALO_W 38                    // TILE_W + 6
#define HALO_H 22                    // TILE_H + 6
#define SROW 88                      // u64 per tile row (80 slots + 8 pad)
#define TILE_SZ (HALO_H * SROW)      // 1936 u64 = 15.5 KB
#define NTHREADS 128
#define CH_PER_BLOCK 16              // 8 channel-pair iterations per block
#define F4_PER_ROW 10                // float4 windows covering [gx0-4, gx0+36)
#define NPAIRS (F4_PER_ROW * HALO_H) // 220 float4-pairs per tile

// Segment-major duplicated layout:
//   tile[r*SROW + k*10 + pos] holds halo column (4k + pos), k=0..7, pos=0..9.
// Compute thread tx reads its 10 taps as 5 aligned LDS.128 from segment k=tx.

__device__ __forceinline__ float4 ldg_f4_guard(const float* p, bool pred) {
    float4 v = make_float4(0.f, 0.f, 0.f, 0.f);
    if (pred) v = *reinterpret_cast<const float4*>(p);
    return v;
}

// Issue the (predicated) global loads for one channel-pair tile into registers.
__device__ __forceinline__ void tile_ldg(const float* __restrict__ xa,
                                         int gx0, int gy0, int tid,
                                         float4 fa[2], float4 fb[2])
{
    #pragma unroll
    for (int e = 0; e < 2; ++e) {
        int j = tid + NTHREADS * e;
        bool valid = (j < NPAIRS);
        int row = j / F4_PER_ROW;                 // constant div (mul-high)
        int c4  = j - row * F4_PER_ROW;
        int gy  = gy0 - PAD + row;
        int gxs = gx0 - 4 + 4 * c4;               // float4-aligned start
        bool inb = valid && ((unsigned)gy < (unsigned)HH) && ((unsigned)gxs < (unsigned)WW);
        const float* pa = xa + (gy << 8) + gxs;
        fa[e] = ldg_f4_guard(pa, inb);
        fb[e] = ldg_f4_guard(pa + HH * WW, inb);
    }
}

// Scatter the register-held float4 pair into the segment-major layout.
// float4 covers halo cols lc0..lc0+3 with lc0 = 4*c4 - 1 (odd). It intersects
// segments k = c4 (pos 0..2), k = c4-1 (pos 3..6), k = c4-2 (pos 7..9).
// Each (k,pos) slot is written by exactly one float4. Guard: 0 <= k <= 7.
__device__ __forceinline__ void tile_sts(u64* __restrict__ buf, int tid,
                                         const float4 fa[2], const float4 fb[2])
{
    #pragma unroll
    for (int e = 0; e < 2; ++e) {
        int j = tid + NTHREADS * e;
        if (j < NPAIRS) {
            int row = j / F4_PER_ROW;
            int c4  = j - row * F4_PER_ROW;
            int rb  = row * SROW;
            u64 v1 = pack2(fa[e].y, fb[e].y);     // col lc0+1
            u64 v2 = pack2(fa[e].z, fb[e].z);     // col lc0+2
            u64 v0 = pack2(fa[e].x, fb[e].x);     // col lc0
            u64 v3 = pack2(fa[e].w, fb[e].w);     // col lc0+3
            // k = c4: positions 0,1 (pair) + 2
            if (c4 <= 7) {
                int base = rb + c4 * 10;
                *reinterpret_cast<ulonglong2*>(&buf[base]) = make_ulonglong2(v1, v2);
                buf[base + 2] = v3;
            }
            // k = c4-1: positions 3 + 4,5 (pair) + 6
            if (c4 >= 1 && c4 <= 8) {
                int base = rb + (c4 - 1) * 10;
                buf[base + 3] = v0;
                *reinterpret_cast<ulonglong2*>(&buf[base + 4]) = make_ulonglong2(v1, v2);
                buf[base + 6] = v3;
            }
            // k = c4-2: positions 7 + 8,9 (pair)
            if (c4 >= 2) {
                int base = rb + (c4 - 2) * 10;
                buf[base + 7] = v0;
                *reinterpret_cast<ulonglong2*>(&buf[base + 8]) = make_ulonglong2(v1, v2);
            }
        }
    }
}

__global__ void __launch_bounds__(NTHREADS, 5)
gauss_smooth_kernel(const float* __restrict__ x,
                    const float* __restrict__ persp,
                    const float* __restrict__ alpha,
                    const float* __restrict__ beta,
                    const float* __restrict__ gamma,
                    float* __restrict__ out)
{
    __shared__ u64 tile[2][TILE_SZ];

    const int tid = threadIdx.x;
    const int tx  = tid & 7;         // column strip (4 output cols each)
    const int ty  = tid >> 3;        // output row within tile (0..15)

    const int b   = blockIdx.z >> 2;
    const int cg  = blockIdx.z & 3;
    const int c0  = cg * CH_PER_BLOCK;
    const int gx0 = blockIdx.x * TILE_W;
    const int gy0 = blockIdx.y * TILE_H;

    const int oy  = gy0 + ty;
    const int ocx = gx0 + tx * 4;

    // ---------------- per-pixel weights (shared across all channels) ----------
    // Unnormalized tap weights {1, t1, t4, t9}; normalize once at the end by 1/S^2.
    const float al = alpha[0];
    const float be = beta[0];
    const float ga = gamma[0];

    u64 T1[4], T4[4], T9[4], INV[4];
    {
        const float* prow = persp + ((size_t)b * HH * WW) + oy * WW + ocx;
        #pragma unroll
        for (int px = 0; px < 4; ++px) {
            float p  = prow[px];
            float z  = fmaf(be, p, ga);
            float sg = __fdividef(1.0f, 1.0f + __expf(-z));
            float sig = fmaxf(al * sg, 1e-4f);
            float u  = __fdividef(0.5f, sig * sig);
            float t1 = __expf(-u);
            float t2 = t1 * t1;
            float t4 = t2 * t2;
            float t8 = t4 * t4;
            float t9 = t8 * t1;
            float S  = 1.0f + 2.0f * (t1 + t4 + t9);
            float inv = __fdividef(1.0f, S);
            float inv2 = inv * inv;
            T1[px]  = pack2(t1, t1);
            T4[px]  = pack2(t4, t4);
            T9[px]  = pack2(t9, t9);
            INV[px] = pack2(inv2, inv2);
        }
    }

    const int sbase = ty * SROW + tx * 10;   // this thread's segment, row ty
    const size_t plane = (size_t)HH * WW;
    const float* xbase = x + ((size_t)(b * CC + c0)) * plane;

    // Prologue: load + stage first channel pair.
    {
        float4 fa[2], fb[2];
        tile_ldg(xbase, gx0, gy0, tid, fa, fb);
        tile_sts(tile[0], tid, fa, fb);
    }
    __syncthreads();

    // ---------------- channel-pair loop (register-pipelined loads) -------------
    #pragma unroll 1
    for (int cp = 0; cp < CH_PER_BLOCK / 2; ++cp) {
        // Issue next tile's LDGs now; latency hidden by the compute below.
        float4 fa[2], fb[2];
        if (cp < CH_PER_BLOCK / 2 - 1) {
            tile_ldg(xbase + (size_t)(2 * cp + 2) * plane, gx0, gy0, tid, fa, fb);
        }

        const u64* cur = tile[cp & 1];

        // Vertical symmetry fold (d-groups: rows ty+d & ty+6-d), then
        // horizontal 7-tap {1,t1,t4,t9}, all packed f32x2.
        u64 acc[4];

        #pragma unroll
        for (int d = 0; d < 4; ++d) {
            u64 g[10];
            if (d < 3) {
                const u64* ra = &cur[sbase + d * SROW];
                const u64* rb = &cur[sbase + (6 - d) * SROW];
                #pragma unroll
                for (int mp = 0; mp < 5; ++mp) {
                    ulonglong2 va = *reinterpret_cast<const ulonglong2*>(&ra[2 * mp]);
                    ulonglong2 vb = *reinterpret_cast<const ulonglong2*>(&rb[2 * mp]);
                    g[2 * mp]     = add2(va.x, vb.x);
                    g[2 * mp + 1] = add2(va.y, vb.y);
                }
            } else {
                const u64* rc = &cur[sbase + 3 * SROW];
                #pragma unroll
                for (int mp = 0; mp < 5; ++mp) {
                    ulonglong2 vc = *reinterpret_cast<const ulonglong2*>(&rc[2 * mp]);
                    g[2 * mp]     = vc.x;
                    g[2 * mp + 1] = vc.y;
                }
            }
            #pragma unroll
            for (int px = 0; px < 4; ++px) {
                u64 s3 = add2(g[px],     g[px + 6]);
                u64 s2 = add2(g[px + 1], g[px + 5]);
                u64 s1 = add2(g[px + 2], g[px + 4]);
                u64 h  = fma2(T9[px], s3, g[px + 3]);
                h      = fma2(T4[px], s2, h);
                h      = fma2(T1[px], s1, h);
                // vertical weight by d-group: d=0 -> t9, 1 -> t4, 2 -> t1, 3 -> 1
                if (d == 0)      acc[px] = mul2(T9[px], h);
                else if (d == 1) acc[px] = fma2(T4[px], h, acc[px]);
                else if (d == 2) acc[px] = fma2(T1[px], h, acc[px]);
                else             acc[px] = add2(h, acc[px]);
            }
        }

        // Normalize and write out: channel c (.x) and c+1 (.y), one float4 each.
        float ax[4], ay[4];
        #pragma unroll
        for (int px = 0; px < 4; ++px) {
            u64 o = mul2(acc[px], INV[px]);
            unpack2(o, ax[px], ay[px]);
        }

        const int c = c0 + 2 * cp;
        float* ob = out + ((size_t)(b * CC + c)) * plane + (oy << 8) + ocx;
        *reinterpret_cast<float4*>(ob)         = make_float4(ax[0], ax[1], ax[2], ax[3]);
        *reinterpret_cast<float4*>(ob + plane) = make_float4(ay[0], ay[1], ay[2], ay[3]);

        __syncthreads();   // all reads of tile[(cp+1)&1] (from iter cp-1) complete
        if (cp < CH_PER_BLOCK / 2 - 1) {
            tile_sts(tile[(cp + 1) & 1], tid, fa, fb);
        }
        __syncthreads();   // staged tile visible before next compute
    }
}

extern "C" void kernel_launch(void* const* d_in, const int* in_sizes, int n_in,
                              void* d_out, int out_size)
{
    const float* x     = (const float*)d_in[0];
    const float* persp = (const float*)d_in[1];
    const float* alpha = (const float*)d_in[2];
    const float* beta  = (const float*)d_in[3];
    const float* gamma = (const float*)d_in[4];
    float* out = (float*)d_out;

    dim3 grid(WW / TILE_W, HH / TILE_H, 4 * (CC / CH_PER_BLOCK)); // (8, 16, 16)
    dim3 block(NTHREADS);
    gauss_smooth_kernel<<<grid, block>>>(x, persp, alpha, beta, gamma, out);
}